// round 1
// baseline (speedup 1.0000x reference)
#include <cuda_runtime.h>

#define HID 256
#define G3 768
#define NB 8192
#define SEQ 49
#define TLEN 50
#define VOCAB 148
#define LATENT 32

#define RB 16     // rows per CTA in step kernel
#define RGA 16    // row-group layer 0
#define RGC 8     // row-group layer 1
#define PRB 16    // rows per CTA in projection
#define PRG 8

// ---- scratch (__device__ globals: allocation-free) ----
__device__ float g_h0[NB * HID];
__device__ float g_h1[NB * HID];
__device__ float g_y[(size_t)NB * SEQ * HID];
__device__ float g_G0[VOCAB * G3];
__device__ float g_Whh0t[HID * G3];
__device__ float g_Wih1t[HID * G3];
__device__ float g_Whh1t[HID * G3];
__device__ float g_W1t[HID * HID];
__device__ float g_W2t[HID * VOCAB];

__device__ __forceinline__ float sigf(float x) { return 1.f / (1.f + expf(-x)); }

// ---- generic transpose into selected scratch matrix ----
// W: R x C row-major  ->  Wt: C x R row-major
__global__ void transpose_sel(const float* __restrict__ W, int R, int C, int sel) {
    __shared__ float tile[32][33];
    float* Wt = (sel == 0) ? g_Whh0t : (sel == 1) ? g_Wih1t : (sel == 2) ? g_Whh1t
              : (sel == 3) ? g_W1t : g_W2t;
    int c = blockIdx.x * 32 + threadIdx.x;
    int r = blockIdx.y * 32 + threadIdx.y;
    if (r < R && c < C) tile[threadIdx.y][threadIdx.x] = W[r * C + c];
    __syncthreads();
    int cc = blockIdx.x * 32 + threadIdx.y;
    int rr = blockIdx.y * 32 + threadIdx.x;
    if (cc < C && rr < R) Wt[cc * R + rr] = tile[threadIdx.x][threadIdx.y];
}

// ---- h init: h[b, 2*HID] = z @ W_lat^T + b_lat ----
__global__ void hinit_k(const float* __restrict__ z, const float* __restrict__ Wlat,
                        const float* __restrict__ blat) {
    int b = blockIdx.x;
    int j = blockIdx.y * blockDim.x + threadIdx.x;  // 0..511
    __shared__ float zs[LATENT];
    if (threadIdx.x < LATENT) zs[threadIdx.x] = z[b * LATENT + threadIdx.x];
    __syncthreads();
    float acc = blat[j];
    const float* w = Wlat + (size_t)j * LATENT;
#pragma unroll
    for (int k = 0; k < LATENT; k++) acc = fmaf(zs[k], w[k], acc);
    if (j < HID) g_h0[(size_t)b * HID + j] = acc;
    else         g_h1[(size_t)b * HID + (j - HID)] = acc;
}

// ---- G0[v, 768] = emb[v] @ W_ih0^T + b_ih0  (teacher-forced input gates) ----
__global__ void g0_k(const float* __restrict__ emb, const float* __restrict__ Wih0,
                     const float* __restrict__ bih0) {
    int v = blockIdx.x;
    int g = blockIdx.y * blockDim.x + threadIdx.x;  // 0..767
    __shared__ float es[HID];
    es[threadIdx.x] = emb[v * HID + threadIdx.x];
    __syncthreads();
    float acc = bih0[g];
    const float* w = Wih0 + (size_t)g * HID;
#pragma unroll 4
    for (int k = 0; k < HID; k++) acc = fmaf(es[k], w[k], acc);
    g_G0[v * G3 + g] = acc;
}

// ---- one GRU timestep: both layers, fused gates, no inter-CTA dependency ----
__global__ __launch_bounds__(256, 1) void step_k(const int* __restrict__ tt,
                                                 const float* __restrict__ bhh0,
                                                 const float* __restrict__ bih1,
                                                 const float* __restrict__ bhh1, int t) {
    __shared__ float h0s[RB * HID];
    __shared__ float h1s[RB * HID];
    int tid = threadIdx.x;
    int r0 = blockIdx.x * RB;
    {
        float4* d0 = (float4*)h0s; const float4* s0 = (const float4*)(g_h0 + (size_t)r0 * HID);
        float4* d1 = (float4*)h1s; const float4* s1 = (const float4*)(g_h1 + (size_t)r0 * HID);
        for (int i = tid; i < RB * HID / 4; i += 256) { d0[i] = s0[i]; d1[i] = s1[i]; }
    }
    __syncthreads();
    const int j = tid;

    // ---- layer 0: gh0 = h0 @ W_hh0^T, gates with gathered gi0 ----
    for (int g = 0; g < RB / RGA; ++g) {
        float ar[RGA], az[RGA], an[RGA];
        float br = bhh0[j], bz = bhh0[HID + j], bn = bhh0[2 * HID + j];
#pragma unroll
        for (int rr = 0; rr < RGA; rr++) { ar[rr] = br; az[rr] = bz; an[rr] = bn; }
        const float* __restrict__ W = g_Whh0t + j;
        const float* hp = h0s + g * RGA * HID;
#pragma unroll 2
        for (int k = 0; k < HID; k++) {
            float w0 = W[0], w1 = W[HID], w2 = W[2 * HID];
            W += G3;
#pragma unroll
            for (int rr = 0; rr < RGA; rr++) {
                float h = hp[rr * HID + k];
                ar[rr] = fmaf(h, w0, ar[rr]);
                az[rr] = fmaf(h, w1, az[rr]);
                an[rr] = fmaf(h, w2, an[rr]);
            }
        }
        float hn[RGA];
#pragma unroll
        for (int rr = 0; rr < RGA; rr++) {
            int r = g * RGA + rr, b = r0 + r;
            int tok = (t == 0) ? 1 : tt[b * TLEN + t];
            const float* gi = g_G0 + tok * G3;
            float rg = sigf(gi[j] + ar[rr]);
            float zg = sigf(gi[HID + j] + az[rr]);
            float nn = tanhf(gi[2 * HID + j] + rg * an[rr]);
            hn[rr] = (1.f - zg) * nn + zg * h0s[r * HID + j];
        }
        __syncthreads();
#pragma unroll
        for (int rr = 0; rr < RGA; rr++) {
            int r = g * RGA + rr;
            h0s[r * HID + j] = hn[rr];
            g_h0[(size_t)(r0 + r) * HID + j] = hn[rr];
        }
    }
    __syncthreads();

    // ---- layer 1: gi1 = h0n @ W_ih1^T, gh1 = h1 @ W_hh1^T ----
    for (int g = 0; g < RB / RGC; ++g) {
        float air[RGC], aiz[RGC], ain[RGC], ahr[RGC], ahz[RGC], ahn[RGC];
        float bi0 = bih1[j], bi1 = bih1[HID + j], bi2 = bih1[2 * HID + j];
        float bh0 = bhh1[j], bh1 = bhh1[HID + j], bh2 = bhh1[2 * HID + j];
#pragma unroll
        for (int rr = 0; rr < RGC; rr++) {
            air[rr] = bi0; aiz[rr] = bi1; ain[rr] = bi2;
            ahr[rr] = bh0; ahz[rr] = bh1; ahn[rr] = bh2;
        }
        const float* __restrict__ Wi = g_Wih1t + j;
        const float* __restrict__ Wh = g_Whh1t + j;
        const float* xp = h0s + g * RGC * HID;
        const float* hp = h1s + g * RGC * HID;
#pragma unroll 2
        for (int k = 0; k < HID; k++) {
            float wi0 = Wi[0], wi1 = Wi[HID], wi2 = Wi[2 * HID]; Wi += G3;
            float wh0 = Wh[0], wh1 = Wh[HID], wh2 = Wh[2 * HID]; Wh += G3;
#pragma unroll
            for (int rr = 0; rr < RGC; rr++) {
                float x = xp[rr * HID + k], h = hp[rr * HID + k];
                air[rr] = fmaf(x, wi0, air[rr]);
                aiz[rr] = fmaf(x, wi1, aiz[rr]);
                ain[rr] = fmaf(x, wi2, ain[rr]);
                ahr[rr] = fmaf(h, wh0, ahr[rr]);
                ahz[rr] = fmaf(h, wh1, ahz[rr]);
                ahn[rr] = fmaf(h, wh2, ahn[rr]);
            }
        }
        float hn[RGC];
#pragma unroll
        for (int rr = 0; rr < RGC; rr++) {
            int r = g * RGC + rr;
            float rg = sigf(air[rr] + ahr[rr]);
            float zg = sigf(aiz[rr] + ahz[rr]);
            float nn = tanhf(ain[rr] + rg * ahn[rr]);
            hn[rr] = (1.f - zg) * nn + zg * h1s[r * HID + j];
        }
        __syncthreads();
#pragma unroll
        for (int rr = 0; rr < RGC; rr++) {
            int r = g * RGC + rr, b = r0 + r;
            h1s[r * HID + j] = hn[rr];
            g_h1[(size_t)b * HID + j] = hn[rr];
            g_y[((size_t)b * SEQ + t) * HID + j] = hn[rr];
        }
    }
}

// ---- fused projection: logits = relu(y @ W1^T + b1) @ W2^T + b2 ----
__global__ __launch_bounds__(256, 1) void proj_k(const float* __restrict__ b1,
                                                 const float* __restrict__ b2,
                                                 float* __restrict__ out) {
    __shared__ float ys[PRB * HID];
    __shared__ float hs[PRB * HID];
    int tid = threadIdx.x;
    size_t row0 = (size_t)blockIdx.x * PRB;
    {
        float4* d = (float4*)ys; const float4* s = (const float4*)(g_y + row0 * HID);
        for (int i = tid; i < PRB * HID / 4; i += 256) d[i] = s[i];
    }
    __syncthreads();
    const int j = tid;
    for (int g = 0; g < PRB / PRG; g++) {
        float a[PRG];
        float bb = b1[j];
#pragma unroll
        for (int rr = 0; rr < PRG; rr++) a[rr] = bb;
        const float* __restrict__ W = g_W1t + j;
        const float* yp = ys + g * PRG * HID;
#pragma unroll 2
        for (int k = 0; k < HID; k++) {
            float w = W[0]; W += HID;
#pragma unroll
            for (int rr = 0; rr < PRG; rr++) a[rr] = fmaf(yp[rr * HID + k], w, a[rr]);
        }
#pragma unroll
        for (int rr = 0; rr < PRG; rr++) hs[(g * PRG + rr) * HID + j] = fmaxf(a[rr], 0.f);
    }
    __syncthreads();
    if (j < VOCAB) {
        for (int g = 0; g < PRB / PRG; g++) {
            float a[PRG];
            float bb = b2[j];
#pragma unroll
            for (int rr = 0; rr < PRG; rr++) a[rr] = bb;
            const float* __restrict__ W = g_W2t + j;
            const float* hp = hs + g * PRG * HID;
#pragma unroll 2
            for (int k = 0; k < HID; k++) {
                float w = W[0]; W += VOCAB;
#pragma unroll
                for (int rr = 0; rr < PRG; rr++) a[rr] = fmaf(hp[rr * HID + k], w, a[rr]);
            }
#pragma unroll
            for (int rr = 0; rr < PRG; rr++)
                out[(row0 + g * PRG + rr) * VOCAB + j] = a[rr];
        }
    }
}

// ---- generated = float(target_tokens[:, 1:]) ----
__global__ void gen_k(const int* __restrict__ tt, float* __restrict__ outg) {
    int i = blockIdx.x * blockDim.x + threadIdx.x;
    if (i < NB * SEQ) {
        int b = i / SEQ, s = i % SEQ;
        outg[i] = (float)tt[b * TLEN + 1 + s];
    }
}

extern "C" void kernel_launch(void* const* d_in, const int* in_sizes, int n_in,
                              void* d_out, int out_size) {
    const float* z    = (const float*)d_in[0];
    const int*   tt   = (const int*)  d_in[1];
    const float* emb  = (const float*)d_in[2];
    const float* Wlat = (const float*)d_in[3];
    const float* blat = (const float*)d_in[4];
    const float* Wih0 = (const float*)d_in[5];
    const float* Whh0 = (const float*)d_in[6];
    const float* bih0 = (const float*)d_in[7];
    // const float* bhh0_unused = (const float*)d_in[8];
    const float* bhh0 = (const float*)d_in[8];
    const float* Wih1 = (const float*)d_in[9];
    const float* Whh1 = (const float*)d_in[10];
    const float* bih1 = (const float*)d_in[11];
    const float* bhh1 = (const float*)d_in[12];
    const float* W1   = (const float*)d_in[13];
    const float* b1   = (const float*)d_in[14];
    const float* W2   = (const float*)d_in[15];
    const float* b2   = (const float*)d_in[16];
    float* out = (float*)d_out;

    dim3 tb(32, 32);
    transpose_sel<<<dim3(8, 24), tb>>>(Whh0, G3, HID, 0);
    transpose_sel<<<dim3(8, 24), tb>>>(Wih1, G3, HID, 1);
    transpose_sel<<<dim3(8, 24), tb>>>(Whh1, G3, HID, 2);
    transpose_sel<<<dim3(8, 8),  tb>>>(W1,  HID, HID, 3);
    transpose_sel<<<dim3(8, 5),  tb>>>(W2,  VOCAB, HID, 4);

    hinit_k<<<dim3(NB, 2), 256>>>(z, Wlat, blat);
    g0_k<<<dim3(VOCAB, 3), 256>>>(emb, Wih0, bih0);

    for (int t = 0; t < SEQ; t++) {
        step_k<<<NB / RB, 256>>>(tt, bhh0, bih1, bhh1, t);
    }

    proj_k<<<(NB * SEQ) / PRB, 256>>>(b1, b2, out);
    gen_k<<<(NB * SEQ + 255) / 256, 256>>>(tt, out + (size_t)NB * SEQ * VOCAB);
}